// round 7
// baseline (speedup 1.0000x reference)
#include <cuda_runtime.h>
#include <stdint.h>

// 12-bit ripple-borrow subtractor on binary (0/1) float spikes.
// Boolean-exact collapse: diffs = bits of ((a-b) & 0xFFF) MSB-first,
// borrow = (a < b). Output: [B*12] diffs row-major, then [B] borrow.
//
// R5: persistent grid-stride version of R4 (which hit the ~6.56 TB/s
// mixed-stream ceiling). Grid = 148 SMs x 4 CTAs, fully resident; each CTA
// streams tiles back-to-back -> no wave-quantization tail, no CTA churn.
// Per-instruction address pattern identical to R4/R1 (the measured-best).

#define TPB 256
#define ROWS_PER_THREAD 2
#define TILE_ROWS (TPB * ROWS_PER_THREAD)
#define NUM_BLOCKS (148 * 4)

__device__ __forceinline__ uint32_t pack12(const uint4& w0, const uint4& w1, const uint4& w2) {
    // index 0 = MSB (bit 11) ... index 11 = LSB (bit 0); inputs are 0.0f/1.0f
    uint32_t v = 0;
    v |= (w0.x ? 1u : 0u) << 11;
    v |= (w0.y ? 1u : 0u) << 10;
    v |= (w0.z ? 1u : 0u) << 9;
    v |= (w0.w ? 1u : 0u) << 8;
    v |= (w1.x ? 1u : 0u) << 7;
    v |= (w1.y ? 1u : 0u) << 6;
    v |= (w1.z ? 1u : 0u) << 5;
    v |= (w1.w ? 1u : 0u) << 4;
    v |= (w2.x ? 1u : 0u) << 3;
    v |= (w2.y ? 1u : 0u) << 2;
    v |= (w2.z ? 1u : 0u) << 1;
    v |= (w2.w ? 1u : 0u);
    return v;
}

__device__ __forceinline__ uint32_t bitf(uint32_t d, int bit) {
    return ((d >> bit) & 1u) * 0x3F800000u;  // 1.0f bits or 0
}

__global__ void __launch_bounds__(TPB) sub12_kernel(
    const uint4* __restrict__ A4,
    const uint4* __restrict__ B4,
    uint4* __restrict__ D4,
    float* __restrict__ Borrow,
    int batch)
{
    const int tid = threadIdx.x;
    const int strideRows = gridDim.x * TILE_ROWS;

    for (int tileBase = blockIdx.x * TILE_ROWS; tileBase < batch; tileBase += strideRows) {
        uint4 a[ROWS_PER_THREAD][3], b[ROWS_PER_THREAD][3];
        int rows[ROWS_PER_THREAD];
        bool valid[ROWS_PER_THREAD];

        // Front-batched loads: all 12 LDG.128 issued before any compute.
#pragma unroll
        for (int r = 0; r < ROWS_PER_THREAD; r++) {
            const int i = tileBase + r * TPB + tid;  // block-strided: best warp pattern
            rows[r] = i;
            valid[r] = (i < batch);
            if (valid[r]) {
                const size_t base = (size_t)i * 3;
                a[r][0] = __ldcs(&A4[base + 0]);
                a[r][1] = __ldcs(&A4[base + 1]);
                a[r][2] = __ldcs(&A4[base + 2]);
                b[r][0] = __ldcs(&B4[base + 0]);
                b[r][1] = __ldcs(&B4[base + 1]);
                b[r][2] = __ldcs(&B4[base + 2]);
            }
        }

#pragma unroll
        for (int r = 0; r < ROWS_PER_THREAD; r++) {
            if (!valid[r]) continue;
            const int i = rows[r];

            const uint32_t ia = pack12(a[r][0], a[r][1], a[r][2]);
            const uint32_t ib = pack12(b[r][0], b[r][1], b[r][2]);
            const uint32_t d  = (ia - ib) & 0xFFFu;

            uint4 o0, o1, o2;
            o0.x = bitf(d, 11); o0.y = bitf(d, 10); o0.z = bitf(d, 9); o0.w = bitf(d, 8);
            o1.x = bitf(d, 7);  o1.y = bitf(d, 6);  o1.z = bitf(d, 5); o1.w = bitf(d, 4);
            o2.x = bitf(d, 3);  o2.y = bitf(d, 2);  o2.z = bitf(d, 1); o2.w = bitf(d, 0);

            const size_t base = (size_t)i * 3;
            __stcs(&D4[base + 0], o0);
            __stcs(&D4[base + 1], o1);
            __stcs(&D4[base + 2], o2);
            __stcs(&Borrow[i], __uint_as_float((ia < ib) ? 0x3F800000u : 0u));
        }
    }
}

extern "C" void kernel_launch(void* const* d_in, const int* in_sizes, int n_in,
                              void* d_out, int out_size)
{
    const uint4* A4 = (const uint4*)d_in[0];
    const uint4* B4 = (const uint4*)d_in[1];
    const int batch = in_sizes[0] / 12;

    float* out = (float*)d_out;
    uint4* D4 = (uint4*)out;
    float* Borrow = out + (size_t)batch * 12;

    // Cap grid at the work size (tiny batches), else fully-resident persistent grid.
    int blocks = NUM_BLOCKS;
    const int tiles = (batch + TILE_ROWS - 1) / TILE_ROWS;
    if (tiles < blocks) blocks = tiles;

    sub12_kernel<<<blocks, TPB>>>(A4, B4, D4, Borrow, batch);
}

// round 8
// speedup vs baseline: 1.0223x; 1.0223x over previous
#include <cuda_runtime.h>
#include <stdint.h>

// 12-bit ripple-borrow subtractor on binary (0/1) float spikes.
// Boolean-exact collapse: diffs = bits of ((a-b) & 0xFFF) MSB-first,
// borrow = (a < b). Output: [B*12] diffs row-major, then [B] borrow.
//
// R7: flat oversubscribed launch (measured best structure), block-strided
// 4 rows/thread, 24 front-batched LDG.128 per thread. Per-warp address
// pattern per instruction identical to R1/R4 (the 6.56 TB/s variants).

#define TPB 256
#define ROWS_PER_THREAD 4
#define TILE_ROWS (TPB * ROWS_PER_THREAD)

__device__ __forceinline__ uint32_t pack12(const uint4& w0, const uint4& w1, const uint4& w2) {
    // index 0 = MSB (bit 11) ... index 11 = LSB (bit 0); inputs are 0.0f/1.0f
    uint32_t v = 0;
    v |= (w0.x ? 1u : 0u) << 11;
    v |= (w0.y ? 1u : 0u) << 10;
    v |= (w0.z ? 1u : 0u) << 9;
    v |= (w0.w ? 1u : 0u) << 8;
    v |= (w1.x ? 1u : 0u) << 7;
    v |= (w1.y ? 1u : 0u) << 6;
    v |= (w1.z ? 1u : 0u) << 5;
    v |= (w1.w ? 1u : 0u) << 4;
    v |= (w2.x ? 1u : 0u) << 3;
    v |= (w2.y ? 1u : 0u) << 2;
    v |= (w2.z ? 1u : 0u) << 1;
    v |= (w2.w ? 1u : 0u);
    return v;
}

__device__ __forceinline__ uint32_t bitf(uint32_t d, int bit) {
    return ((d >> bit) & 1u) * 0x3F800000u;  // 1.0f bits or 0
}

__global__ void __launch_bounds__(TPB) sub12_kernel(
    const uint4* __restrict__ A4,
    const uint4* __restrict__ B4,
    uint4* __restrict__ D4,
    float* __restrict__ Borrow,
    int batch)
{
    const int tid = threadIdx.x;
    const int tileBase = blockIdx.x * TILE_ROWS;

    uint4 a[ROWS_PER_THREAD][3], b[ROWS_PER_THREAD][3];
    bool valid[ROWS_PER_THREAD];

    // Front-batched loads: all 24 LDG.128 issued before any compute.
#pragma unroll
    for (int r = 0; r < ROWS_PER_THREAD; r++) {
        const int i = tileBase + r * TPB + tid;  // block-strided warp pattern
        valid[r] = (i < batch);
        if (valid[r]) {
            const size_t base = (size_t)i * 3;
            a[r][0] = __ldcs(&A4[base + 0]);
            a[r][1] = __ldcs(&A4[base + 1]);
            a[r][2] = __ldcs(&A4[base + 2]);
            b[r][0] = __ldcs(&B4[base + 0]);
            b[r][1] = __ldcs(&B4[base + 1]);
            b[r][2] = __ldcs(&B4[base + 2]);
        }
    }

#pragma unroll
    for (int r = 0; r < ROWS_PER_THREAD; r++) {
        if (!valid[r]) continue;
        const int i = tileBase + r * TPB + tid;

        const uint32_t ia = pack12(a[r][0], a[r][1], a[r][2]);
        const uint32_t ib = pack12(b[r][0], b[r][1], b[r][2]);
        const uint32_t d  = (ia - ib) & 0xFFFu;

        uint4 o0, o1, o2;
        o0.x = bitf(d, 11); o0.y = bitf(d, 10); o0.z = bitf(d, 9); o0.w = bitf(d, 8);
        o1.x = bitf(d, 7);  o1.y = bitf(d, 6);  o1.z = bitf(d, 5); o1.w = bitf(d, 4);
        o2.x = bitf(d, 3);  o2.y = bitf(d, 2);  o2.z = bitf(d, 1); o2.w = bitf(d, 0);

        const size_t base = (size_t)i * 3;
        __stcs(&D4[base + 0], o0);
        __stcs(&D4[base + 1], o1);
        __stcs(&D4[base + 2], o2);
        __stcs(&Borrow[i], __uint_as_float((ia < ib) ? 0x3F800000u : 0u));
    }
}

extern "C" void kernel_launch(void* const* d_in, const int* in_sizes, int n_in,
                              void* d_out, int out_size)
{
    const uint4* A4 = (const uint4*)d_in[0];
    const uint4* B4 = (const uint4*)d_in[1];
    const int batch = in_sizes[0] / 12;

    float* out = (float*)d_out;
    uint4* D4 = (uint4*)out;
    float* Borrow = out + (size_t)batch * 12;

    const int blocks = (batch + TILE_ROWS - 1) / TILE_ROWS;
    sub12_kernel<<<blocks, TPB>>>(A4, B4, D4, Borrow, batch);
}

// round 9
// speedup vs baseline: 1.1100x; 1.0857x over previous
#include <cuda_runtime.h>
#include <stdint.h>

// 12-bit ripple-borrow subtractor on binary (0/1) float spikes.
// Boolean-exact collapse: diffs = bits of ((a-b) & 0xFFF) MSB-first,
// borrow = (a < b). Output: [B*12] diffs row-major, then [B] borrow.
//
// R8 = R4 (measured best: 6.56 TB/s DRAM ceiling, occ 40%) + unpredicated
// full-tile fast path (BATCH divides the 512-row tile evenly).
// Findings so far: 6.56 TB/s is the mixed 65/35 R/W stream ceiling; reached
// whenever occ >= ~40% with flat oversubscribed launch. Persistent grids and
// RPT>=4 both regress (loop serialization / occupancy below threshold).

#define TPB 256
#define ROWS_PER_THREAD 2
#define TILE_ROWS (TPB * ROWS_PER_THREAD)

__device__ __forceinline__ uint32_t pack12(const uint4& w0, const uint4& w1, const uint4& w2) {
    // index 0 = MSB (bit 11) ... index 11 = LSB (bit 0); inputs are 0.0f/1.0f
    uint32_t v = 0;
    v |= (w0.x ? 1u : 0u) << 11;
    v |= (w0.y ? 1u : 0u) << 10;
    v |= (w0.z ? 1u : 0u) << 9;
    v |= (w0.w ? 1u : 0u) << 8;
    v |= (w1.x ? 1u : 0u) << 7;
    v |= (w1.y ? 1u : 0u) << 6;
    v |= (w1.z ? 1u : 0u) << 5;
    v |= (w1.w ? 1u : 0u) << 4;
    v |= (w2.x ? 1u : 0u) << 3;
    v |= (w2.y ? 1u : 0u) << 2;
    v |= (w2.z ? 1u : 0u) << 1;
    v |= (w2.w ? 1u : 0u);
    return v;
}

__device__ __forceinline__ uint32_t bitf(uint32_t d, int bit) {
    return ((d >> bit) & 1u) * 0x3F800000u;  // 1.0f bits or 0
}

__device__ __forceinline__ void do_row(
    const uint4* __restrict__ A4, const uint4* __restrict__ B4,
    uint4* __restrict__ D4, float* __restrict__ Borrow, int i0, int i1)
{
    // Two rows, loads front-batched before compute.
    const size_t p0 = (size_t)i0 * 3, p1 = (size_t)i1 * 3;
    const uint4 a00 = __ldcs(&A4[p0 + 0]);
    const uint4 a01 = __ldcs(&A4[p0 + 1]);
    const uint4 a02 = __ldcs(&A4[p0 + 2]);
    const uint4 b00 = __ldcs(&B4[p0 + 0]);
    const uint4 b01 = __ldcs(&B4[p0 + 1]);
    const uint4 b02 = __ldcs(&B4[p0 + 2]);
    const uint4 a10 = __ldcs(&A4[p1 + 0]);
    const uint4 a11 = __ldcs(&A4[p1 + 1]);
    const uint4 a12 = __ldcs(&A4[p1 + 2]);
    const uint4 b10 = __ldcs(&B4[p1 + 0]);
    const uint4 b11 = __ldcs(&B4[p1 + 1]);
    const uint4 b12 = __ldcs(&B4[p1 + 2]);

    const uint32_t ia0 = pack12(a00, a01, a02);
    const uint32_t ib0 = pack12(b00, b01, b02);
    const uint32_t d0  = (ia0 - ib0) & 0xFFFu;
    const uint32_t ia1 = pack12(a10, a11, a12);
    const uint32_t ib1 = pack12(b10, b11, b12);
    const uint32_t d1  = (ia1 - ib1) & 0xFFFu;

    uint4 o;
    o.x = bitf(d0, 11); o.y = bitf(d0, 10); o.z = bitf(d0, 9); o.w = bitf(d0, 8);
    __stcs(&D4[p0 + 0], o);
    o.x = bitf(d0, 7);  o.y = bitf(d0, 6);  o.z = bitf(d0, 5); o.w = bitf(d0, 4);
    __stcs(&D4[p0 + 1], o);
    o.x = bitf(d0, 3);  o.y = bitf(d0, 2);  o.z = bitf(d0, 1); o.w = bitf(d0, 0);
    __stcs(&D4[p0 + 2], o);
    __stcs(&Borrow[i0], __uint_as_float((ia0 < ib0) ? 0x3F800000u : 0u));

    o.x = bitf(d1, 11); o.y = bitf(d1, 10); o.z = bitf(d1, 9); o.w = bitf(d1, 8);
    __stcs(&D4[p1 + 0], o);
    o.x = bitf(d1, 7);  o.y = bitf(d1, 6);  o.z = bitf(d1, 5); o.w = bitf(d1, 4);
    __stcs(&D4[p1 + 1], o);
    o.x = bitf(d1, 3);  o.y = bitf(d1, 2);  o.z = bitf(d1, 1); o.w = bitf(d1, 0);
    __stcs(&D4[p1 + 2], o);
    __stcs(&Borrow[i1], __uint_as_float((ia1 < ib1) ? 0x3F800000u : 0u));
}

__global__ void __launch_bounds__(TPB) sub12_kernel(
    const uint4* __restrict__ A4,
    const uint4* __restrict__ B4,
    uint4* __restrict__ D4,
    float* __restrict__ Borrow,
    int batch)
{
    const int tid = threadIdx.x;
    const int tileBase = blockIdx.x * TILE_ROWS;

    if (tileBase + TILE_ROWS <= batch) {
        // Full tile: no predication, straight batched LDG/STG streams.
        do_row(A4, B4, D4, Borrow, tileBase + tid, tileBase + TPB + tid);
    } else {
        // Ragged tail (not hit for BATCH % 512 == 0, kept for generality).
#pragma unroll
        for (int r = 0; r < ROWS_PER_THREAD; r++) {
            const int i = tileBase + r * TPB + tid;
            if (i < batch) do_row(A4, B4, D4, Borrow, i, i);  // i1==i0: redundant but safe
        }
    }
}

extern "C" void kernel_launch(void* const* d_in, const int* in_sizes, int n_in,
                              void* d_out, int out_size)
{
    const uint4* A4 = (const uint4*)d_in[0];
    const uint4* B4 = (const uint4*)d_in[1];
    const int batch = in_sizes[0] / 12;

    float* out = (float*)d_out;
    uint4* D4 = (uint4*)out;
    float* Borrow = out + (size_t)batch * 12;

    const int blocks = (batch + TILE_ROWS - 1) / TILE_ROWS;
    sub12_kernel<<<blocks, TPB>>>(A4, B4, D4, Borrow, batch);
}

// round 10
// speedup vs baseline: 1.1585x; 1.0437x over previous
#include <cuda_runtime.h>
#include <stdint.h>

// 12-bit ripple-borrow subtractor on binary (0/1) float spikes.
// Boolean-exact collapse: diffs = bits of ((a-b) & 0xFFF) MSB-first,
// borrow = (a < b). Output: [B*12] diffs row-major, then [B] borrow.
//
// FINAL (= R4, verified best 92.9us bench / 88.1us ncu / 6.56 TB/s DRAM):
// flat oversubscribed launch, 2 rows/thread block-strided (R1 warp address
// pattern per instruction), __ldcs/__stcs streaming hints, all loads
// front-batched, compute into DISTINCT output registers, stores batched last.
// Session findings: 6.56 TB/s is the mixed 65/35 R/W stream ceiling (hit by
// every variant with occ>=40%); traffic (620.7MB) is irreducible; persistent
// grids, smem staging, RPT>=4, and register-reusing store chains all regress.

#define TPB 256
#define ROWS_PER_THREAD 2

__device__ __forceinline__ uint32_t pack12(const uint4& w0, const uint4& w1, const uint4& w2) {
    // index 0 = MSB (bit 11) ... index 11 = LSB (bit 0); inputs are 0.0f/1.0f
    uint32_t v = 0;
    v |= (w0.x ? 1u : 0u) << 11;
    v |= (w0.y ? 1u : 0u) << 10;
    v |= (w0.z ? 1u : 0u) << 9;
    v |= (w0.w ? 1u : 0u) << 8;
    v |= (w1.x ? 1u : 0u) << 7;
    v |= (w1.y ? 1u : 0u) << 6;
    v |= (w1.z ? 1u : 0u) << 5;
    v |= (w1.w ? 1u : 0u) << 4;
    v |= (w2.x ? 1u : 0u) << 3;
    v |= (w2.y ? 1u : 0u) << 2;
    v |= (w2.z ? 1u : 0u) << 1;
    v |= (w2.w ? 1u : 0u);
    return v;
}

__device__ __forceinline__ uint32_t bitf(uint32_t d, int bit) {
    return ((d >> bit) & 1u) * 0x3F800000u;  // 1.0f bits or 0
}

__global__ void __launch_bounds__(TPB) sub12_kernel(
    const uint4* __restrict__ A4,
    const uint4* __restrict__ B4,
    uint4* __restrict__ D4,
    float* __restrict__ Borrow,
    int batch)
{
    const int tileBase = blockIdx.x * (TPB * ROWS_PER_THREAD);
    const int tid = threadIdx.x;

    int rows[ROWS_PER_THREAD];
    uint4 a[ROWS_PER_THREAD][3], b[ROWS_PER_THREAD][3];
    bool valid[ROWS_PER_THREAD];

    // Front-batched loads: all 12 LDG.128 issued before any compute.
#pragma unroll
    for (int r = 0; r < ROWS_PER_THREAD; r++) {
        const int i = tileBase + r * TPB + tid;  // block-strided: R1 warp pattern
        rows[r] = i;
        valid[r] = (i < batch);
        if (valid[r]) {
            a[r][0] = __ldcs(&A4[(size_t)i * 3 + 0]);
            a[r][1] = __ldcs(&A4[(size_t)i * 3 + 1]);
            a[r][2] = __ldcs(&A4[(size_t)i * 3 + 2]);
            b[r][0] = __ldcs(&B4[(size_t)i * 3 + 0]);
            b[r][1] = __ldcs(&B4[(size_t)i * 3 + 1]);
            b[r][2] = __ldcs(&B4[(size_t)i * 3 + 2]);
        }
    }

#pragma unroll
    for (int r = 0; r < ROWS_PER_THREAD; r++) {
        if (!valid[r]) continue;
        const int i = rows[r];

        const uint32_t ia = pack12(a[r][0], a[r][1], a[r][2]);
        const uint32_t ib = pack12(b[r][0], b[r][1], b[r][2]);
        const uint32_t d  = (ia - ib) & 0xFFFu;

        uint4 o0, o1, o2;
        o0.x = bitf(d, 11); o0.y = bitf(d, 10); o0.z = bitf(d, 9); o0.w = bitf(d, 8);
        o1.x = bitf(d, 7);  o1.y = bitf(d, 6);  o1.z = bitf(d, 5); o1.w = bitf(d, 4);
        o2.x = bitf(d, 3);  o2.y = bitf(d, 2);  o2.z = bitf(d, 1); o2.w = bitf(d, 0);

        __stcs(&D4[(size_t)i * 3 + 0], o0);
        __stcs(&D4[(size_t)i * 3 + 1], o1);
        __stcs(&D4[(size_t)i * 3 + 2], o2);
        __stcs(&Borrow[i], __uint_as_float((ia < ib) ? 0x3F800000u : 0u));
    }
}

extern "C" void kernel_launch(void* const* d_in, const int* in_sizes, int n_in,
                              void* d_out, int out_size)
{
    const uint4* A4 = (const uint4*)d_in[0];
    const uint4* B4 = (const uint4*)d_in[1];
    const int batch = in_sizes[0] / 12;

    float* out = (float*)d_out;
    uint4* D4 = (uint4*)out;
    float* Borrow = out + (size_t)batch * 12;

    const int rowsPerBlock = TPB * ROWS_PER_THREAD;
    const int blocks = (batch + rowsPerBlock - 1) / rowsPerBlock;
    sub12_kernel<<<blocks, TPB>>>(A4, B4, D4, Borrow, batch);
}